// round 1
// baseline (speedup 1.0000x reference)
#include <cuda_runtime.h>
#include <math.h>

// ---------------- problem constants ----------------
#define BATCH   8
#define CDIM    192
#define HEADS   6
#define HD      32
#define WSZ     8
#define NTOK    64          // tokens per window
#define NWIN    512         // total windows (8 * 8 * 8)
#define ROWS    32768       // NWIN * NTOK
#define CH3     576         // 3*CDIM
#define FF      768         // 4*CDIM
#define HW      4096        // 64*64
#define IMGW    64

// ---------------- scratch (device globals; no allocation allowed) ----------------
__device__ float g_S  [ROWS * (size_t)CDIM];   // LN1 output (shortcut), window-token-major
__device__ float g_QKV[ROWS * (size_t)CH3];    // qkv
__device__ float g_O  [ROWS * (size_t)CDIM];   // attention output (pre-proj)
__device__ float g_X2 [ROWS * (size_t)CDIM];   // shortcut + proj
__device__ float g_H  [ROWS * (size_t)FF];     // gelu(fc1) output
__device__ float g_mu [ROWS];
__device__ float g_rs [ROWS];

// ---------------- kernel 1: LN1 + window partition ----------------
// block per window; dynamic smem tile 64x192 (stride 193 -> conflict free)
__global__ void __launch_bounds__(256)
ln1_kernel(const float* __restrict__ x, const float* __restrict__ g,
           const float* __restrict__ b)
{
    extern __shared__ float sm[];
    float* tile = sm;               // 64 * 193
    float* smu  = sm + 64 * 193;    // 64
    float* srs  = smu + 64;         // 64

    int win = blockIdx.x;
    int bi  = win >> 6;
    int wy  = (win >> 3) & 7;
    int wx  = win & 7;
    const float* xb = x + (size_t)bi * CDIM * HW;

    for (int i = threadIdx.x; i < NTOK * CDIM; i += blockDim.x) {
        int c = i >> 6;
        int n = i & 63;
        int iy = n >> 3, ix = n & 7;
        int hw = ((wy << 3) + iy) * IMGW + (wx << 3) + ix;
        tile[n * 193 + c] = xb[(size_t)c * HW + hw];
    }
    __syncthreads();

    if (threadIdx.x < NTOK) {
        int n = threadIdx.x;
        float s = 0.f, ss = 0.f;
        #pragma unroll 4
        for (int c = 0; c < CDIM; c++) {
            float v = tile[n * 193 + c];
            s += v; ss += v * v;
        }
        float mu  = s * (1.0f / CDIM);
        float var = ss * (1.0f / CDIM) - mu * mu;
        smu[n] = mu;
        srs[n] = rsqrtf(fmaxf(var, 0.f) + 1e-5f);
    }
    __syncthreads();

    float* outp = g_S + (size_t)win * NTOK * CDIM;
    for (int i = threadIdx.x; i < NTOK * CDIM; i += blockDim.x) {
        int n = i / CDIM, c = i - n * CDIM;
        outp[i] = (tile[n * 193 + c] - smu[n]) * srs[n] * g[c] + b[c];
    }
}

// ---------------- generic fp32 GEMM: Out[r,j] = epi( sum_k A[r,k]*W[j,k] + bias[j] ) ----------------
// MODE 0: A=g_S,  out=g_QKV                         (K=192, N=576)
// MODE 1: A=g_O,  out=g_X2 = g_S + res              (K=192, N=192)
// MODE 2: A=LN2(g_X2), out=g_H = gelu(.)            (K=192, N=768)
// MODE 3: A=g_H,  out=d_out (NCHW scatter) = g_X2+. (K=768, N=192)
template<int MODE, int K>
__global__ void __launch_bounds__(256)
gemm_kernel(const float* __restrict__ W, const float* __restrict__ bias,
            const float* __restrict__ lng, const float* __restrict__ lnb,
            float* __restrict__ OutExt)
{
    constexpr int BM = 128, BN = 64, BK = 16;
    __shared__ float As[BK][BM + 4];
    __shared__ float Bs[BK][BN + 4];

    const float* A = (MODE == 0) ? g_S : (MODE == 1) ? g_O : (MODE == 2) ? g_X2 : g_H;

    int tid = threadIdx.x;
    int tx = tid & 15, ty = tid >> 4;
    int rbase = blockIdx.x * BM;
    int cbase = blockIdx.y * BN;

    float acc[8][4];
    #pragma unroll
    for (int i = 0; i < 8; i++)
        #pragma unroll
        for (int j = 0; j < 4; j++) acc[i][j] = 0.f;

    for (int kt = 0; kt < K; kt += BK) {
        #pragma unroll
        for (int t = 0; t < 2; t++) {
            int q   = tid + t * 256;
            int row = q >> 2;
            int kq  = (q & 3) << 2;
            float4 v = *reinterpret_cast<const float4*>(
                A + (size_t)(rbase + row) * K + kt + kq);
            if (MODE == 2) {
                float m = g_mu[rbase + row], r = g_rs[rbase + row];
                float4 gg = *reinterpret_cast<const float4*>(lng + kt + kq);
                float4 bb = *reinterpret_cast<const float4*>(lnb + kt + kq);
                v.x = (v.x - m) * r * gg.x + bb.x;
                v.y = (v.y - m) * r * gg.y + bb.y;
                v.z = (v.z - m) * r * gg.z + bb.z;
                v.w = (v.w - m) * r * gg.w + bb.w;
            }
            As[kq + 0][row] = v.x; As[kq + 1][row] = v.y;
            As[kq + 2][row] = v.z; As[kq + 3][row] = v.w;
        }
        {
            int j  = tid >> 2;
            int kq = (tid & 3) << 2;
            float4 v = *reinterpret_cast<const float4*>(
                W + (size_t)(cbase + j) * K + kt + kq);
            Bs[kq + 0][j] = v.x; Bs[kq + 1][j] = v.y;
            Bs[kq + 2][j] = v.z; Bs[kq + 3][j] = v.w;
        }
        __syncthreads();

        #pragma unroll
        for (int k = 0; k < BK; k++) {
            float a[8], bfr[4];
            #pragma unroll
            for (int i = 0; i < 8; i++) a[i] = As[k][ty * 8 + i];
            #pragma unroll
            for (int j = 0; j < 4; j++) bfr[j] = Bs[k][tx * 4 + j];
            #pragma unroll
            for (int i = 0; i < 8; i++)
                #pragma unroll
                for (int j = 0; j < 4; j++)
                    acc[i][j] = fmaf(a[i], bfr[j], acc[i][j]);
        }
        __syncthreads();
    }

    #pragma unroll
    for (int i = 0; i < 8; i++) {
        int r = rbase + ty * 8 + i;
        #pragma unroll
        for (int j = 0; j < 4; j++) {
            int c = cbase + tx * 4 + j;
            float v = acc[i][j] + bias[c];
            if (MODE == 0) {
                g_QKV[(size_t)r * CH3 + c] = v;
            } else if (MODE == 1) {
                g_X2[(size_t)r * CDIM + c] = g_S[(size_t)r * CDIM + c] + v;
            } else if (MODE == 2) {
                g_H[(size_t)r * FF + c] = 0.5f * v * (1.0f + erff(v * 0.70710678118654752f));
            } else {
                v += g_X2[(size_t)r * CDIM + c];
                int win = r >> 6, n = r & 63;
                int bb = win >> 6, wy = (win >> 3) & 7, wx = win & 7;
                int iy = n >> 3, ix = n & 7;
                int hw = ((wy << 3) + iy) * IMGW + (wx << 3) + ix;
                OutExt[((size_t)bb * CDIM + c) * HW + hw] = v;
            }
        }
    }
}

// ---------------- LN2 row stats ----------------
__global__ void __launch_bounds__(256)
ln2_stats_kernel()
{
    int r    = (blockIdx.x * blockDim.x + threadIdx.x) >> 5;
    int lane = threadIdx.x & 31;
    if (r >= ROWS) return;
    const float* row = g_X2 + (size_t)r * CDIM;
    float s = 0.f, ss = 0.f;
    #pragma unroll
    for (int c = lane; c < CDIM; c += 32) {
        float v = row[c];
        s += v; ss += v * v;
    }
    #pragma unroll
    for (int o = 16; o > 0; o >>= 1) {
        s  += __shfl_xor_sync(0xffffffffu, s,  o);
        ss += __shfl_xor_sync(0xffffffffu, ss, o);
    }
    if (lane == 0) {
        float mu  = s * (1.0f / CDIM);
        float var = ss * (1.0f / CDIM) - mu * mu;
        g_mu[r] = mu;
        g_rs[r] = rsqrtf(fmaxf(var, 0.f) + 1e-5f);
    }
}

// ---------------- attention: one block per (window, head) ----------------
__global__ void __launch_bounds__(256)
attn_kernel(const float* __restrict__ rpb, const float* __restrict__ temp)
{
    extern __shared__ float sm[];
    float* s_q = sm;                 // 64*33
    float* s_k = s_q + 64 * 33;      // 64*33
    float* s_v = s_k + 64 * 33;      // 64*36 (float4-aligned rows)
    float* s_a = s_v + 64 * 36;      // 64*65
    float* s_t = s_a + 64 * 65;      // 225*6

    int blk = blockIdx.x;
    int win = blk / HEADS;
    int h   = blk - win * HEADS;
    int tid = threadIdx.x;
    int wid = tid >> 5, lane = tid & 31;

    for (int i = tid; i < 225 * HEADS; i += 256) s_t[i] = rpb[i];
    float tmp = temp[h];
    size_t base = (size_t)win * NTOK;

    // load q,k,v (head slice) + l2-normalize q,k. warp per row.
    for (int n = wid; n < NTOK; n += 8) {
        const float* qp = g_QKV + (base + n) * CH3 + h * HD;
        float qv = qp[lane];
        float kv = qp[192 + lane];
        float vv = qp[384 + lane];
        float qs = qv * qv, ks = kv * kv;
        #pragma unroll
        for (int o = 16; o > 0; o >>= 1) {
            qs += __shfl_xor_sync(0xffffffffu, qs, o);
            ks += __shfl_xor_sync(0xffffffffu, ks, o);
        }
        float qi = 1.0f / fmaxf(sqrtf(qs), 1e-12f);
        float ki = 1.0f / fmaxf(sqrtf(ks), 1e-12f);
        s_q[n * 33 + lane] = qv * qi;
        s_k[n * 33 + lane] = kv * ki;
        s_v[n * 36 + lane] = vv;
    }
    __syncthreads();

    // logits: 4x4 microtile per thread, 64x64 total
    {
        int n0 = (tid >> 4) << 2;
        int m0 = (tid & 15) << 2;
        float acc[4][4];
        #pragma unroll
        for (int i = 0; i < 4; i++)
            #pragma unroll
            for (int j = 0; j < 4; j++) acc[i][j] = 0.f;
        #pragma unroll 8
        for (int d = 0; d < HD; d++) {
            float a[4], b[4];
            #pragma unroll
            for (int i = 0; i < 4; i++) a[i] = s_q[(n0 + i) * 33 + d];
            #pragma unroll
            for (int j = 0; j < 4; j++) b[j] = s_k[(m0 + j) * 33 + d];
            #pragma unroll
            for (int i = 0; i < 4; i++)
                #pragma unroll
                for (int j = 0; j < 4; j++)
                    acc[i][j] = fmaf(a[i], b[j], acc[i][j]);
        }
        #pragma unroll
        for (int i = 0; i < 4; i++)
            #pragma unroll
            for (int j = 0; j < 4; j++)
                s_a[(n0 + i) * 65 + m0 + j] = acc[i][j] * tmp;
    }
    __syncthreads();

    // per-row: exact top-16 threshold, mask(-100), +rpb, softmax. warp per row.
    for (int n = wid; n < NTOK; n += 8) {
        int iy = n >> 3, ix = n & 7;
        float r0 = s_a[n * 65 + lane];
        float r1 = s_a[n * 65 + 32 + lane];
        float v0 = r0, v1 = r1;
        // remove the 15 largest (one instance each); remaining max = 16th largest
        #pragma unroll 1
        for (int it = 0; it < 15; it++) {
            float m = fmaxf(v0, v1);
            #pragma unroll
            for (int o = 16; o > 0; o >>= 1) m = fmaxf(m, __shfl_xor_sync(0xffffffffu, m, o));
            unsigned b0 = __ballot_sync(0xffffffffu, v0 == m);
            if (b0) {
                if (lane == (__ffs(b0) - 1)) v0 = -1e30f;
            } else {
                unsigned b1 = __ballot_sync(0xffffffffu, v1 == m);
                if (lane == (__ffs(b1) - 1)) v1 = -1e30f;
            }
        }
        float kth = fmaxf(v0, v1);
        #pragma unroll
        for (int o = 16; o > 0; o >>= 1) kth = fmaxf(kth, __shfl_xor_sync(0xffffffffu, kth, o));

        int m0 = lane, m1 = lane + 32;
        int jy = m0 >> 3, jx = m0 & 7;
        float e0 = ((r0 >= kth) ? r0 : -100.0f)
                 + s_t[((iy - jy + 7) * 15 + (ix - jx + 7)) * HEADS + h];
        jy = m1 >> 3; jx = m1 & 7;
        float e1 = ((r1 >= kth) ? r1 : -100.0f)
                 + s_t[((iy - jy + 7) * 15 + (ix - jx + 7)) * HEADS + h];

        float mx = fmaxf(e0, e1);
        #pragma unroll
        for (int o = 16; o > 0; o >>= 1) mx = fmaxf(mx, __shfl_xor_sync(0xffffffffu, mx, o));
        float p0 = expf(e0 - mx), p1 = expf(e1 - mx);
        float s = p0 + p1;
        #pragma unroll
        for (int o = 16; o > 0; o >>= 1) s += __shfl_xor_sync(0xffffffffu, s, o);
        float inv = 1.0f / s;
        s_a[n * 65 + lane]      = p0 * inv;
        s_a[n * 65 + 32 + lane] = p1 * inv;
    }
    __syncthreads();

    // AV: thread = 2 rows x 4 dims
    {
        int d0 = (tid & 7) << 2;
        int n0 = (tid >> 3) << 1;
        float a0[4] = {0.f, 0.f, 0.f, 0.f};
        float a1[4] = {0.f, 0.f, 0.f, 0.f};
        #pragma unroll 8
        for (int m = 0; m < NTOK; m++) {
            float p0 = s_a[n0 * 65 + m];
            float p1 = s_a[(n0 + 1) * 65 + m];
            float4 vv = *reinterpret_cast<const float4*>(&s_v[m * 36 + d0]);
            a0[0] = fmaf(p0, vv.x, a0[0]); a0[1] = fmaf(p0, vv.y, a0[1]);
            a0[2] = fmaf(p0, vv.z, a0[2]); a0[3] = fmaf(p0, vv.w, a0[3]);
            a1[0] = fmaf(p1, vv.x, a1[0]); a1[1] = fmaf(p1, vv.y, a1[1]);
            a1[2] = fmaf(p1, vv.z, a1[2]); a1[3] = fmaf(p1, vv.w, a1[3]);
        }
        float* op = g_O + (base + n0) * CDIM + h * HD + d0;
        op[0] = a0[0]; op[1] = a0[1]; op[2] = a0[2]; op[3] = a0[3];
        op += CDIM;
        op[0] = a1[0]; op[1] = a1[1]; op[2] = a1[2]; op[3] = a1[3];
    }
}

// ---------------- launch ----------------
extern "C" void kernel_launch(void* const* d_in, const int* in_sizes, int n_in,
                              void* d_out, int out_size)
{
    const float* x      = (const float*)d_in[0];
    const float* n1g    = (const float*)d_in[1];
    const float* n1b    = (const float*)d_in[2];
    const float* qkv_w  = (const float*)d_in[3];
    const float* qkv_b  = (const float*)d_in[4];
    const float* proj_w = (const float*)d_in[5];
    const float* proj_b = (const float*)d_in[6];
    const float* rpb    = (const float*)d_in[7];
    const float* temp   = (const float*)d_in[8];
    const float* n2g    = (const float*)d_in[9];
    const float* n2b    = (const float*)d_in[10];
    const float* fc1_w  = (const float*)d_in[11];
    const float* fc1_b  = (const float*)d_in[12];
    const float* fc2_w  = (const float*)d_in[13];
    const float* fc2_b  = (const float*)d_in[14];
    float* out = (float*)d_out;

    const int LN1_SMEM  = (64 * 193 + 128) * 4;                    // 49920 B
    const int ATTN_SMEM = (64 * 33 * 2 + 64 * 36 + 64 * 65 + 225 * 6) * 4; // 48152 B
    cudaFuncSetAttribute(ln1_kernel,  cudaFuncAttributeMaxDynamicSharedMemorySize, LN1_SMEM);
    cudaFuncSetAttribute(attn_kernel, cudaFuncAttributeMaxDynamicSharedMemorySize, ATTN_SMEM);

    // 1. LN1 + window partition -> g_S
    ln1_kernel<<<NWIN, 256, LN1_SMEM>>>(x, n1g, n1b);

    // 2. QKV gemm -> g_QKV
    gemm_kernel<0, 192><<<dim3(ROWS / 128, CH3 / 64), 256>>>(qkv_w, qkv_b, nullptr, nullptr, nullptr);

    // 3. attention -> g_O
    attn_kernel<<<NWIN * HEADS, 256, ATTN_SMEM>>>(rpb, temp);

    // 4. proj + residual -> g_X2
    gemm_kernel<1, 192><<<dim3(ROWS / 128, CDIM / 64), 256>>>(proj_w, proj_b, nullptr, nullptr, nullptr);

    // 5. LN2 stats
    ln2_stats_kernel<<<(ROWS * 32) / 256, 256>>>();

    // 6. fc1 + GELU -> g_H
    gemm_kernel<2, 192><<<dim3(ROWS / 128, FF / 64), 256>>>(fc1_w, fc1_b, n2g, n2b, nullptr);

    // 7. fc2 + residual + window-reverse + NCHW scatter -> d_out
    gemm_kernel<3, 768><<<dim3(ROWS / 128, CDIM / 64), 256>>>(fc2_w, fc2_b, nullptr, nullptr, out);
}

// round 6
// speedup vs baseline: 1.5449x; 1.5449x over previous
#include <cuda_runtime.h>
#include <cuda_bf16.h>
#include <math.h>
#include <stdint.h>

// ---------------- problem constants ----------------
#define BATCH   8
#define CDIM    192
#define HEADS   6
#define HD      32
#define NTOK    64
#define NWIN    512
#define ROWS    32768
#define CH3     576
#define FF      768
#define HW      4096
#define IMGW    64

// ---------------- scratch ----------------
__device__ float g_S  [ROWS * (size_t)CDIM];   // LN1 out (shortcut); reused as final token-major Y
__device__ float g_QKV[ROWS * (size_t)CH3];
__device__ float g_O  [ROWS * (size_t)CDIM];
__device__ float g_X2 [ROWS * (size_t)CDIM];
__device__ float g_H  [ROWS * (size_t)FF];
__device__ float g_mu [ROWS];
__device__ float g_rs [ROWS];

// ---------------- helpers ----------------
__device__ __forceinline__ uint32_t smem_to_u32(const void* p) {
    uint32_t a;
    asm("{ .reg .u64 t; cvta.to.shared.u64 t, %1; cvt.u32.u64 %0, t; }" : "=r"(a) : "l"(p));
    return a;
}

__device__ __forceinline__ void ldm4(uint32_t* r, uint32_t addr) {
    asm volatile("ldmatrix.sync.aligned.m8n8.x4.shared.b16 {%0,%1,%2,%3}, [%4];"
                 : "=r"(r[0]), "=r"(r[1]), "=r"(r[2]), "=r"(r[3]) : "r"(addr));
}

__device__ __forceinline__ void mma_bf16(float* c, const uint32_t* a, uint32_t b0, uint32_t b1) {
    asm volatile("mma.sync.aligned.m16n8k16.row.col.f32.bf16.bf16.f32 "
                 "{%0,%1,%2,%3}, {%4,%5,%6,%7}, {%8,%9}, {%0,%1,%2,%3};"
                 : "+f"(c[0]), "+f"(c[1]), "+f"(c[2]), "+f"(c[3])
                 : "r"(a[0]), "r"(a[1]), "r"(a[2]), "r"(a[3]), "r"(b0), "r"(b1));
}

__device__ __forceinline__ void split_pair(float x, float y, unsigned& h, unsigned& l) {
    __nv_bfloat16 hx = __float2bfloat16(x);
    __nv_bfloat16 hy = __float2bfloat16(y);
    __nv_bfloat16 lx = __float2bfloat16(x - __bfloat162float(hx));
    __nv_bfloat16 ly = __float2bfloat16(y - __bfloat162float(hy));
    __nv_bfloat162 hh = __halves2bfloat162(hx, hy);
    __nv_bfloat162 ll = __halves2bfloat162(lx, ly);
    h = *reinterpret_cast<unsigned*>(&hh);
    l = *reinterpret_cast<unsigned*>(&ll);
}

// smem plane layout (bytes); bf16, row stride 40 elems (80B -> ldmatrix conflict-free)
#define AH_OFF 0
#define AL_OFF 10240
#define BH_OFF 20480
#define BL_OFF 25600
#define GSMEM  33280    // also fits the 128x65 fp32 epilogue tile

// ---------------- bf16x3 HMMA GEMM: Out = epi(A @ W^T + bias) ----------------
// MODE 0: A=g_S       -> g_QKV                      (K=192, N=576)
// MODE 1: A=g_O       -> g_X2 = g_S + .             (K=192, N=192)
// MODE 2: A=LN2(g_X2) -> g_H = gelu(.)              (K=192, N=768)
// MODE 3: A=g_H       -> g_S (token-major) = g_X2+. (K=768, N=192)
template<int MODE, int K>
__global__ void __launch_bounds__(256)
gemm_mma(const float* __restrict__ W, const float* __restrict__ bias,
         const float* __restrict__ lng, const float* __restrict__ lnb) {
    extern __shared__ char sm[];
    uint32_t sb = smem_to_u32(sm);
    __nv_bfloat16* Ah = reinterpret_cast<__nv_bfloat16*>(sm + AH_OFF);
    __nv_bfloat16* Al = reinterpret_cast<__nv_bfloat16*>(sm + AL_OFF);
    __nv_bfloat16* Bh = reinterpret_cast<__nv_bfloat16*>(sm + BH_OFF);
    __nv_bfloat16* Bl = reinterpret_cast<__nv_bfloat16*>(sm + BL_OFF);

    const float* A = (MODE == 0) ? g_S : (MODE == 1) ? g_O : (MODE == 2) ? g_X2 : g_H;

    int tid = threadIdx.x;
    int lane = tid & 31, w = tid >> 5;
    int wm = (w >> 1) * 32, wn = (w & 1) * 32;
    int rbase = blockIdx.x * 128, cbase = blockIdx.y * 64;

    // ldmatrix lane address components
    uint32_t aRow = (lane & 7) + ((lane >> 3) & 1) * 8;
    uint32_t aK   = (lane >> 4) * 8;
    uint32_t bN   = ((lane >> 4) & 1) * 8 + (lane & 7);
    uint32_t bK   = ((lane >> 3) & 1) * 8;

    float acc[2][4][4];
    #pragma unroll
    for (int mi = 0; mi < 2; mi++)
        #pragma unroll
        for (int ni = 0; ni < 4; ni++)
            #pragma unroll
            for (int j = 0; j < 4; j++) acc[mi][ni][j] = 0.f;

    constexpr int NC = K / 32;
    for (int c = 0; c < NC; c++) {
        int kt = c * 32;
        // ---- load A chunk (128x32) as hi/lo bf16 planes ----
        #pragma unroll
        for (int i = 0; i < 4; i++) {
            int g = i * 256 + tid;
            int row = g >> 3, kq = (g & 7) * 4;
            float4 v = *reinterpret_cast<const float4*>(A + (size_t)(rbase + row) * K + kt + kq);
            if (MODE == 2) {
                float m = g_mu[rbase + row], rr = g_rs[rbase + row];
                float4 gg = *reinterpret_cast<const float4*>(lng + kt + kq);
                float4 bb = *reinterpret_cast<const float4*>(lnb + kt + kq);
                v.x = (v.x - m) * rr * gg.x + bb.x;
                v.y = (v.y - m) * rr * gg.y + bb.y;
                v.z = (v.z - m) * rr * gg.z + bb.z;
                v.w = (v.w - m) * rr * gg.w + bb.w;
            }
            uint2 h, l;
            split_pair(v.x, v.y, h.x, l.x);
            split_pair(v.z, v.w, h.y, l.y);
            int eo = row * 40 + kq;
            *reinterpret_cast<uint2*>(Ah + eo) = h;
            *reinterpret_cast<uint2*>(Al + eo) = l;
        }
        // ---- load B chunk (64x32) ----
        #pragma unroll
        for (int i = 0; i < 2; i++) {
            int g = i * 256 + tid;
            int row = g >> 3, kq = (g & 7) * 4;
            float4 v = *reinterpret_cast<const float4*>(W + (size_t)(cbase + row) * K + kt + kq);
            uint2 h, l;
            split_pair(v.x, v.y, h.x, l.x);
            split_pair(v.z, v.w, h.y, l.y);
            int eo = row * 40 + kq;
            *reinterpret_cast<uint2*>(Bh + eo) = h;
            *reinterpret_cast<uint2*>(Bl + eo) = l;
        }
        __syncthreads();

        // ---- compute: 2 k16 steps ----
        #pragma unroll
        for (int kk = 0; kk < 32; kk += 16) {
            uint32_t ah[2][4], al[2][4], bh[2][4], bl[2][4];
            #pragma unroll
            for (int mi = 0; mi < 2; mi++) {
                uint32_t off = ((wm + mi * 16 + aRow) * 40 + kk + aK) * 2;
                ldm4(ah[mi], sb + AH_OFF + off);
                ldm4(al[mi], sb + AL_OFF + off);
            }
            #pragma unroll
            for (int p = 0; p < 2; p++) {
                uint32_t off = ((wn + p * 16 + bN) * 40 + kk + bK) * 2;
                ldm4(bh[p], sb + BH_OFF + off);
                ldm4(bl[p], sb + BL_OFF + off);
            }
            #pragma unroll
            for (int mi = 0; mi < 2; mi++)
                #pragma unroll
                for (int ni = 0; ni < 4; ni++) {
                    int p = ni >> 1, o = (ni & 1) * 2;
                    mma_bf16(acc[mi][ni], ah[mi], bh[p][o], bh[p][o + 1]);
                    mma_bf16(acc[mi][ni], ah[mi], bl[p][o], bl[p][o + 1]);
                    mma_bf16(acc[mi][ni], al[mi], bh[p][o], bh[p][o + 1]);
                }
        }
        __syncthreads();
    }

    // ---- epilogue: frags -> smem fp32 tile -> coalesced global ----
    float* st = reinterpret_cast<float*>(sm);   // 128 x 65
    #pragma unroll
    for (int mi = 0; mi < 2; mi++)
        #pragma unroll
        for (int ni = 0; ni < 4; ni++) {
            int row = wm + mi * 16 + (lane >> 2);
            int col = wn + ni * 8 + (lane & 3) * 2;
            st[row * 65 + col]       = acc[mi][ni][0];
            st[row * 65 + col + 1]   = acc[mi][ni][1];
            st[(row + 8) * 65 + col]     = acc[mi][ni][2];
            st[(row + 8) * 65 + col + 1] = acc[mi][ni][3];
        }
    __syncthreads();

    for (int i = tid; i < 128 * 64; i += 256) {
        int row = i >> 6, j = i & 63;
        int r = rbase + row, cc = cbase + j;
        float v = st[row * 65 + j] + bias[cc];
        if (MODE == 0) {
            g_QKV[(size_t)r * CH3 + cc] = v;
        } else if (MODE == 1) {
            g_X2[(size_t)r * CDIM + cc] = g_S[(size_t)r * CDIM + cc] + v;
        } else if (MODE == 2) {
            g_H[(size_t)r * FF + cc] = 0.5f * v * (1.0f + erff(v * 0.70710678118654752f));
        } else {
            g_S[(size_t)r * CDIM + cc] = g_X2[(size_t)r * CDIM + cc] + v;
        }
    }
}

// ---------------- kernel: LN1 + window partition ----------------
__global__ void __launch_bounds__(256)
ln1_kernel(const float* __restrict__ x, const float* __restrict__ g,
           const float* __restrict__ b) {
    extern __shared__ float smf[];
    float* tile = smf;
    float* smu  = smf + 64 * 193;
    float* srs  = smu + 64;

    int win = blockIdx.x;
    int bi = win >> 6, wy = (win >> 3) & 7, wx = win & 7;
    const float* xb = x + (size_t)bi * CDIM * HW;

    for (int i = threadIdx.x; i < NTOK * CDIM; i += blockDim.x) {
        int c = i >> 6, n = i & 63;
        int iy = n >> 3, ix = n & 7;
        int hw = ((wy << 3) + iy) * IMGW + (wx << 3) + ix;
        tile[n * 193 + c] = xb[(size_t)c * HW + hw];
    }
    __syncthreads();
    if (threadIdx.x < NTOK) {
        int n = threadIdx.x;
        float s = 0.f, ss = 0.f;
        #pragma unroll 4
        for (int c = 0; c < CDIM; c++) {
            float v = tile[n * 193 + c];
            s += v; ss += v * v;
        }
        float mu = s * (1.0f / CDIM);
        float var = ss * (1.0f / CDIM) - mu * mu;
        smu[n] = mu;
        srs[n] = rsqrtf(fmaxf(var, 0.f) + 1e-5f);
    }
    __syncthreads();
    float* outp = g_S + (size_t)win * NTOK * CDIM;
    for (int i = threadIdx.x; i < NTOK * CDIM; i += blockDim.x) {
        int n = i / CDIM, c = i - n * CDIM;
        outp[i] = (tile[n * 193 + c] - smu[n]) * srs[n] * g[c] + b[c];
    }
}

// ---------------- LN2 row stats ----------------
__global__ void __launch_bounds__(256)
ln2_stats_kernel() {
    int r = (blockIdx.x * blockDim.x + threadIdx.x) >> 5;
    int lane = threadIdx.x & 31;
    if (r >= ROWS) return;
    const float* row = g_X2 + (size_t)r * CDIM;
    float s = 0.f, ss = 0.f;
    #pragma unroll
    for (int c = lane; c < CDIM; c += 32) {
        float v = row[c];
        s += v; ss += v * v;
    }
    #pragma unroll
    for (int o = 16; o > 0; o >>= 1) {
        s  += __shfl_xor_sync(0xffffffffu, s,  o);
        ss += __shfl_xor_sync(0xffffffffu, ss, o);
    }
    if (lane == 0) {
        float mu = s * (1.0f / CDIM);
        float var = ss * (1.0f / CDIM) - mu * mu;
        g_mu[r] = mu;
        g_rs[r] = rsqrtf(fmaxf(var, 0.f) + 1e-5f);
    }
}

// ---------------- attention ----------------
__global__ void __launch_bounds__(256)
attn_kernel(const float* __restrict__ rpb, const float* __restrict__ temp) {
    extern __shared__ float smf[];
    float* s_q = smf;
    float* s_k = s_q + 64 * 33;
    float* s_v = s_k + 64 * 33;
    float* s_a = s_v + 64 * 36;
    float* s_t = s_a + 64 * 65;

    int blk = blockIdx.x;
    int win = blk / HEADS;
    int h = blk - win * HEADS;
    int tid = threadIdx.x;
    int wid = tid >> 5, lane = tid & 31;

    for (int i = tid; i < 225 * HEADS; i += 256) s_t[i] = rpb[i];
    float tmp = temp[h];
    size_t base = (size_t)win * NTOK;

    for (int n = wid; n < NTOK; n += 8) {
        const float* qp = g_QKV + (base + n) * CH3 + h * HD;
        float qv = qp[lane];
        float kv = qp[192 + lane];
        float vv = qp[384 + lane];
        float qs = qv * qv, ks = kv * kv;
        #pragma unroll
        for (int o = 16; o > 0; o >>= 1) {
            qs += __shfl_xor_sync(0xffffffffu, qs, o);
            ks += __shfl_xor_sync(0xffffffffu, ks, o);
        }
        float qi = 1.0f / fmaxf(sqrtf(qs), 1e-12f);
        float ki = 1.0f / fmaxf(sqrtf(ks), 1e-12f);
        s_q[n * 33 + lane] = qv * qi;
        s_k[n * 33 + lane] = kv * ki;
        s_v[n * 36 + lane] = vv;
    }
    __syncthreads();

    {
        int n0 = (tid >> 4) << 2;
        int m0 = (tid & 15) << 2;
        float acc[4][4];
        #pragma unroll
        for (int i = 0; i < 4; i++)
            #pragma unroll
            for (int j = 0; j < 4; j++) acc[i][j] = 0.f;
        #pragma unroll 8
        for (int d = 0; d < HD; d++) {
            float a[4], b[4];
            #pragma unroll
            for (int i = 0; i < 4; i++) a[i] = s_q[(n0 + i) * 33 + d];
            #pragma unroll
            for (int j = 0; j < 4; j++) b[j] = s_k[(m0 + j) * 33 + d];
            #pragma unroll
            for (int i = 0; i < 4; i++)
                #pragma unroll
                for (int j = 0; j < 4; j++)
                    acc[i][j] = fmaf(a[i], b[j], acc[i][j]);
        }
        #pragma unroll
        for (int i = 0; i < 4; i++)
            #pragma unroll
            for (int j = 0; j < 4; j++)
                s_a[(n0 + i) * 65 + m0 + j] = acc[i][j] * tmp;
    }
    __syncthreads();

    for (int n = wid; n < NTOK; n += 8) {
        int iy = n >> 3, ix = n & 7;
        float r0 = s_a[n * 65 + lane];
        float r1 = s_a[n * 65 + 32 + lane];
        float v0 = r0, v1 = r1;
        #pragma unroll 1
        for (int it = 0; it < 15; it++) {
            float m = fmaxf(v0, v1);
            #pragma unroll
            for (int o = 16; o > 0; o >>= 1) m = fmaxf(m, __shfl_xor_sync(0xffffffffu, m, o));
            unsigned b0 = __ballot_sync(0xffffffffu, v0 == m);
            if (b0) {
                if (lane == (__ffs(b0) - 1)) v0 = -1e30f;
            } else {
                unsigned b1 = __ballot_sync(0xffffffffu, v1 == m);
                if (lane == (__ffs(b1) - 1)) v1 = -1e30f;
            }
        }
        float kth = fmaxf(v0, v1);
        #pragma unroll
        for (int o = 16; o > 0; o >>= 1) kth = fmaxf(kth, __shfl_xor_sync(0xffffffffu, kth, o));

        int m0 = lane, m1 = lane + 32;
        int jy = m0 >> 3, jx = m0 & 7;
        float e0 = ((r0 >= kth) ? r0 : -100.0f)
                 + s_t[((iy - jy + 7) * 15 + (ix - jx + 7)) * HEADS + h];
        jy = m1 >> 3; jx = m1 & 7;
        float e1 = ((r1 >= kth) ? r1 : -100.0f)
                 + s_t[((iy - jy + 7) * 15 + (ix - jx + 7)) * HEADS + h];

        float mx = fmaxf(e0, e1);
        #pragma unroll
        for (int o = 16; o > 0; o >>= 1) mx = fmaxf(mx, __shfl_xor_sync(0xffffffffu, mx, o));
        float p0 = expf(e0 - mx), p1 = expf(e1 - mx);
        float s = p0 + p1;
        #pragma unroll
        for (int o = 16; o > 0; o >>= 1) s += __shfl_xor_sync(0xffffffffu, s, o);
        float inv = 1.0f / s;
        s_a[n * 65 + lane]      = p0 * inv;
        s_a[n * 65 + 32 + lane] = p1 * inv;
    }
    __syncthreads();

    {
        int d0 = (tid & 7) << 2;
        int n0 = (tid >> 3) << 1;
        float a0[4] = {0.f, 0.f, 0.f, 0.f};
        float a1[4] = {0.f, 0.f, 0.f, 0.f};
        #pragma unroll 8
        for (int m = 0; m < NTOK; m++) {
            float p0 = s_a[n0 * 65 + m];
            float p1 = s_a[(n0 + 1) * 65 + m];
            float4 vv = *reinterpret_cast<const float4*>(&s_v[m * 36 + d0]);
            a0[0] = fmaf(p0, vv.x, a0[0]); a0[1] = fmaf(p0, vv.y, a0[1]);
            a0[2] = fmaf(p0, vv.z, a0[2]); a0[3] = fmaf(p0, vv.w, a0[3]);
            a1[0] = fmaf(p1, vv.x, a1[0]); a1[1] = fmaf(p1, vv.y, a1[1]);
            a1[2] = fmaf(p1, vv.z, a1[2]); a1[3] = fmaf(p1, vv.w, a1[3]);
        }
        float* op = g_O + (base + n0) * CDIM + h * HD + d0;
        op[0] = a0[0]; op[1] = a0[1]; op[2] = a0[2]; op[3] = a0[3];
        op += CDIM;
        op[0] = a1[0]; op[1] = a1[1]; op[2] = a1[2]; op[3] = a1[3];
    }
}

// ---------------- final transpose: g_S (token-major Y) -> NCHW out ----------------
__global__ void __launch_bounds__(256)
out_tr_kernel(float* __restrict__ out) {
    extern __shared__ float smf[];
    float* tile = smf;  // 64 x 193
    int win = blockIdx.x;
    int bi = win >> 6, wy = (win >> 3) & 7, wx = win & 7;
    const float* src = g_S + (size_t)win * NTOK * CDIM;
    for (int i = threadIdx.x; i < NTOK * CDIM; i += 256) {
        int n = i / CDIM, c = i - n * CDIM;
        tile[n * 193 + c] = src[i];
    }
    __syncthreads();
    float* ob = out + (size_t)bi * CDIM * HW;
    for (int i = threadIdx.x; i < NTOK * CDIM; i += 256) {
        int c = i >> 6, n = i & 63;
        int iy = n >> 3, ix = n & 7;
        int hw = ((wy << 3) + iy) * IMGW + (wx << 3) + ix;
        ob[(size_t)c * HW + hw] = tile[n * 193 + c];
    }
}

// ---------------- launch ----------------
extern "C" void kernel_launch(void* const* d_in, const int* in_sizes, int n_in,
                              void* d_out, int out_size) {
    const float* x      = (const float*)d_in[0];
    const float* n1g    = (const float*)d_in[1];
    const float* n1b    = (const float*)d_in[2];
    const float* qkv_w  = (const float*)d_in[3];
    const float* qkv_b  = (const float*)d_in[4];
    const float* proj_w = (const float*)d_in[5];
    const float* proj_b = (const float*)d_in[6];
    const float* rpb    = (const float*)d_in[7];
    const float* temp   = (const float*)d_in[8];
    const float* n2g    = (const float*)d_in[9];
    const float* n2b    = (const float*)d_in[10];
    const float* fc1_w  = (const float*)d_in[11];
    const float* fc1_b  = (const float*)d_in[12];
    const float* fc2_w  = (const float*)d_in[13];
    const float* fc2_b  = (const float*)d_in[14];
    float* out = (float*)d_out;

    const int LN1_SMEM  = (64 * 193 + 128) * 4;
    const int ATTN_SMEM = (64 * 33 * 2 + 64 * 36 + 64 * 65 + 225 * 6) * 4;
    const int TR_SMEM   = 64 * 193 * 4;
    cudaFuncSetAttribute(ln1_kernel,    cudaFuncAttributeMaxDynamicSharedMemorySize, LN1_SMEM);
    cudaFuncSetAttribute(attn_kernel,   cudaFuncAttributeMaxDynamicSharedMemorySize, ATTN_SMEM);
    cudaFuncSetAttribute(out_tr_kernel, cudaFuncAttributeMaxDynamicSharedMemorySize, TR_SMEM);

    ln1_kernel<<<NWIN, 256, LN1_SMEM>>>(x, n1g, n1b);
    gemm_mma<0, 192><<<dim3(ROWS / 128, CH3 / 64), 256, GSMEM>>>(qkv_w, qkv_b, nullptr, nullptr);
    attn_kernel<<<NWIN * HEADS, 256, ATTN_SMEM>>>(rpb, temp);
    gemm_mma<1, 192><<<dim3(ROWS / 128, CDIM / 64), 256, GSMEM>>>(proj_w, proj_b, nullptr, nullptr);
    ln2_stats_kernel<<<(ROWS * 32) / 256, 256>>>();
    gemm_mma<2, 192><<<dim3(ROWS / 128, FF / 64), 256, GSMEM>>>(fc1_w, fc1_b, n2g, n2b);
    gemm_mma<3, 768><<<dim3(ROWS / 128, CDIM / 64), 256, GSMEM>>>(fc2_w, fc2_b, nullptr, nullptr);
    out_tr_kernel<<<NWIN, 256, TR_SMEM>>>(out);
}

// round 7
// speedup vs baseline: 1.5775x; 1.0211x over previous
#include <cuda_runtime.h>
#include <cuda_bf16.h>
#include <math.h>
#include <stdint.h>

// ---------------- problem constants ----------------
#define BATCH   8
#define CDIM    192
#define HEADS   6
#define HD      32
#define NTOK    64
#define NWIN    512
#define ROWS    32768
#define CH3     576
#define FF      768
#define HW      4096
#define IMGW    64

// weight plane offsets (elements)
#define OFF_QKV  0
#define OFF_PROJ 110592
#define OFF_FC1  147456
#define OFF_FC2  294912
#define WTOT     442368

// ---------------- scratch ----------------
__device__ float g_S  [ROWS * (size_t)CDIM];   // LN1 fp32 (shortcut); reused as final token-major Y
__device__ float g_QKV[ROWS * (size_t)CH3];
__device__ float g_X2 [ROWS * (size_t)CDIM];

__device__ __nv_bfloat16 g_Sh[ROWS * (size_t)CDIM], g_Sl[ROWS * (size_t)CDIM];
__device__ __nv_bfloat16 g_Oh[ROWS * (size_t)CDIM], g_Ol[ROWS * (size_t)CDIM];
__device__ __nv_bfloat16 g_Nh[ROWS * (size_t)CDIM], g_Nl[ROWS * (size_t)CDIM];
__device__ __nv_bfloat16 g_Hh[ROWS * (size_t)FF],   g_Hl[ROWS * (size_t)FF];
__device__ __nv_bfloat16 g_Wh[WTOT], g_Wl[WTOT];

// ---------------- helpers ----------------
__device__ __forceinline__ uint32_t smem_to_u32(const void* p) {
    uint32_t a;
    asm("{ .reg .u64 t; cvta.to.shared.u64 t, %1; cvt.u32.u64 %0, t; }" : "=r"(a) : "l"(p));
    return a;
}
__device__ __forceinline__ void ldm4(uint32_t* r, uint32_t addr) {
    asm volatile("ldmatrix.sync.aligned.m8n8.x4.shared.b16 {%0,%1,%2,%3}, [%4];"
                 : "=r"(r[0]), "=r"(r[1]), "=r"(r[2]), "=r"(r[3]) : "r"(addr));
}
__device__ __forceinline__ void mma_bf16(float* c, const uint32_t* a, uint32_t b0, uint32_t b1) {
    asm volatile("mma.sync.aligned.m16n8k16.row.col.f32.bf16.bf16.f32 "
                 "{%0,%1,%2,%3}, {%4,%5,%6,%7}, {%8,%9}, {%0,%1,%2,%3};"
                 : "+f"(c[0]), "+f"(c[1]), "+f"(c[2]), "+f"(c[3])
                 : "r"(a[0]), "r"(a[1]), "r"(a[2]), "r"(a[3]), "r"(b0), "r"(b1));
}
__device__ __forceinline__ void splitf(float v, __nv_bfloat16& h, __nv_bfloat16& l) {
    h = __float2bfloat16(v);
    l = __float2bfloat16(v - __bfloat162float(h));
}
#define CP16(sdst, gsrc) \
    asm volatile("cp.async.ca.shared.global [%0], [%1], 16;" :: "r"(sdst), "l"(gsrc) : "memory")
#define CP_COMMIT() asm volatile("cp.async.commit_group;" ::: "memory")

// smem per stage (bytes): Ah 10240 | Al 10240 | Bh 5120 | Bl 5120
#define AH_OFF 0
#define AL_OFF 10240
#define BH_OFF 20480
#define BL_OFF 25600
#define STG    30720
#define GSMEM  61440   // 2 stages; also covers the 128x65 fp32 epilogue tile (33280)

// ---------------- bf16x3 HMMA GEMM with cp.async pipeline ----------------
// MODE 0: A=g_Sh/l, B=W[qkv]  -> g_QKV fp32                    (K=192, N=576)
// MODE 1: A=g_Oh/l, B=W[proj] -> g_X2 = g_S + .  fp32          (K=192, N=192)
// MODE 2: A=g_Nh/l, B=W[fc1]  -> g_Hh/l = split(gelu(.))       (K=192, N=768)
// MODE 3: A=g_Hh/l, B=W[fc2]  -> g_S (token-major) = g_X2 + .  (K=768, N=192)
template<int MODE, int K>
__global__ void __launch_bounds__(256)
gemm_mma(const float* __restrict__ bias) {
    extern __shared__ char sm[];
    uint32_t sb = smem_to_u32(sm);

    const __nv_bfloat16* Ah_g = (MODE == 0) ? g_Sh : (MODE == 1) ? g_Oh : (MODE == 2) ? g_Nh : g_Hh;
    const __nv_bfloat16* Al_g = (MODE == 0) ? g_Sl : (MODE == 1) ? g_Ol : (MODE == 2) ? g_Nl : g_Hl;
    constexpr int WOFF = (MODE == 0) ? OFF_QKV : (MODE == 1) ? OFF_PROJ : (MODE == 2) ? OFF_FC1 : OFF_FC2;
    const __nv_bfloat16* Bh_g = g_Wh + WOFF;
    const __nv_bfloat16* Bl_g = g_Wl + WOFF;

    int tid = threadIdx.x;
    int lane = tid & 31, w = tid >> 5;
    int wm = (w >> 1) * 32, wn = (w & 1) * 32;
    int rbase = blockIdx.x * 128, cbase = blockIdx.y * 64;

    uint32_t aRow = (lane & 7) + ((lane >> 3) & 1) * 8;
    uint32_t aK   = (lane >> 4) * 8;
    uint32_t bN   = ((lane >> 4) & 1) * 8 + (lane & 7);
    uint32_t bK   = ((lane >> 3) & 1) * 8;

    float acc[2][4][4];
    #pragma unroll
    for (int mi = 0; mi < 2; mi++)
        #pragma unroll
        for (int ni = 0; ni < 4; ni++)
            #pragma unroll
            for (int j = 0; j < 4; j++) acc[mi][ni][j] = 0.f;

    // copy one 32-k stage (A 128x32 hi/lo, B 64x32 hi/lo) via cp.async
    auto copy_stage = [&](int st, int kt) {
        uint32_t base = sb + st * STG;
        #pragma unroll
        for (int i = 0; i < 2; i++) {
            int gq = i * 256 + tid;
            int r = gq >> 2, s2 = gq & 3;
            size_t go = (size_t)(rbase + r) * K + kt + s2 * 8;
            uint32_t so = (uint32_t)(r * 40 + s2 * 8) * 2;
            CP16(base + AH_OFF + so, Ah_g + go);
            CP16(base + AL_OFF + so, Al_g + go);
        }
        {
            int r = tid >> 2, s2 = tid & 3;
            size_t go = (size_t)(cbase + r) * K + kt + s2 * 8;
            uint32_t so = (uint32_t)(r * 40 + s2 * 8) * 2;
            CP16(base + BH_OFF + so, Bh_g + go);
            CP16(base + BL_OFF + so, Bl_g + go);
        }
        CP_COMMIT();
    };

    constexpr int NC = K / 32;
    copy_stage(0, 0);

    for (int c = 0; c < NC; c++) {
        if (c + 1 < NC) {
            copy_stage((c + 1) & 1, (c + 1) * 32);
            asm volatile("cp.async.wait_group 1;" ::: "memory");
        } else {
            asm volatile("cp.async.wait_group 0;" ::: "memory");
        }
        __syncthreads();

        uint32_t stb = sb + (c & 1) * STG;
        #pragma unroll
        for (int kk = 0; kk < 32; kk += 16) {
            uint32_t ah[2][4], al[2][4], bh[2][4], bl[2][4];
            #pragma unroll
            for (int mi = 0; mi < 2; mi++) {
                uint32_t off = ((wm + mi * 16 + aRow) * 40 + kk + aK) * 2;
                ldm4(ah[mi], stb + AH_OFF + off);
                ldm4(al[mi], stb + AL_OFF + off);
            }
            #pragma unroll
            for (int p = 0; p < 2; p++) {
                uint32_t off = ((wn + p * 16 + bN) * 40 + kk + bK) * 2;
                ldm4(bh[p], stb + BH_OFF + off);
                ldm4(bl[p], stb + BL_OFF + off);
            }
            #pragma unroll
            for (int mi = 0; mi < 2; mi++)
                #pragma unroll
                for (int ni = 0; ni < 4; ni++) {
                    int p = ni >> 1, o = (ni & 1) * 2;
                    mma_bf16(acc[mi][ni], ah[mi], bh[p][o], bh[p][o + 1]);
                    mma_bf16(acc[mi][ni], ah[mi], bl[p][o], bl[p][o + 1]);
                    mma_bf16(acc[mi][ni], al[mi], bh[p][o], bh[p][o + 1]);
                }
        }
        __syncthreads();
    }

    // ---- epilogue: frags -> smem fp32 tile -> coalesced global ----
    float* st = reinterpret_cast<float*>(sm);   // 128 x 65
    #pragma unroll
    for (int mi = 0; mi < 2; mi++)
        #pragma unroll
        for (int ni = 0; ni < 4; ni++) {
            int row = wm + mi * 16 + (lane >> 2);
            int col = wn + ni * 8 + (lane & 3) * 2;
            st[row * 65 + col]           = acc[mi][ni][0];
            st[row * 65 + col + 1]       = acc[mi][ni][1];
            st[(row + 8) * 65 + col]     = acc[mi][ni][2];
            st[(row + 8) * 65 + col + 1] = acc[mi][ni][3];
        }
    __syncthreads();

    for (int i = tid; i < 128 * 64; i += 256) {
        int row = i >> 6, j = i & 63;
        int r = rbase + row, cc = cbase + j;
        float v = st[row * 65 + j] + bias[cc];
        if (MODE == 0) {
            g_QKV[(size_t)r * CH3 + cc] = v;
        } else if (MODE == 1) {
            g_X2[(size_t)r * CDIM + cc] = g_S[(size_t)r * CDIM + cc] + v;
        } else if (MODE == 2) {
            float a = 0.5f * v * (1.0f + erff(v * 0.70710678118654752f));
            __nv_bfloat16 hh, ll;
            splitf(a, hh, ll);
            g_Hh[(size_t)r * FF + cc] = hh;
            g_Hl[(size_t)r * FF + cc] = ll;
        } else {
            g_S[(size_t)r * CDIM + cc] = g_X2[(size_t)r * CDIM + cc] + v;
        }
    }
}

// ---------------- weight conversion: fp32 -> bf16 hi/lo planes ----------------
__global__ void __launch_bounds__(256)
wconv_kernel(const float* __restrict__ qkv_w, const float* __restrict__ proj_w,
             const float* __restrict__ fc1_w, const float* __restrict__ fc2_w) {
    int idx = blockIdx.x * 256 + threadIdx.x;
    if (idx >= WTOT / 4) return;
    int i4 = idx * 4;
    const float* src;
    int off;
    if (i4 < OFF_PROJ)      { src = qkv_w;  off = i4; }
    else if (i4 < OFF_FC1)  { src = proj_w; off = i4 - OFF_PROJ; }
    else if (i4 < OFF_FC2)  { src = fc1_w;  off = i4 - OFF_FC1; }
    else                    { src = fc2_w;  off = i4 - OFF_FC2; }
    float4 v = *reinterpret_cast<const float4*>(src + off);
    __nv_bfloat16 h[4], l[4];
    splitf(v.x, h[0], l[0]); splitf(v.y, h[1], l[1]);
    splitf(v.z, h[2], l[2]); splitf(v.w, h[3], l[3]);
    *reinterpret_cast<uint2*>(g_Wh + i4) = *reinterpret_cast<uint2*>(h);
    *reinterpret_cast<uint2*>(g_Wl + i4) = *reinterpret_cast<uint2*>(l);
}

// ---------------- LN1 + window partition (fp32 + planes) ----------------
__global__ void __launch_bounds__(256)
ln1_kernel(const float* __restrict__ x, const float* __restrict__ g,
           const float* __restrict__ b) {
    extern __shared__ float smf[];
    float* tile = smf;
    float* smu  = smf + 64 * 193;
    float* srs  = smu + 64;

    int win = blockIdx.x;
    int bi = win >> 6, wy = (win >> 3) & 7, wx = win & 7;
    const float* xb = x + (size_t)bi * CDIM * HW;

    for (int i = threadIdx.x; i < NTOK * CDIM; i += blockDim.x) {
        int c = i >> 6, n = i & 63;
        int iy = n >> 3, ix = n & 7;
        int hw = ((wy << 3) + iy) * IMGW + (wx << 3) + ix;
        tile[n * 193 + c] = xb[(size_t)c * HW + hw];
    }
    __syncthreads();
    if (threadIdx.x < NTOK) {
        int n = threadIdx.x;
        float s = 0.f, ss = 0.f;
        #pragma unroll 4
        for (int c = 0; c < CDIM; c++) {
            float v = tile[n * 193 + c];
            s += v; ss += v * v;
        }
        float mu = s * (1.0f / CDIM);
        float var = ss * (1.0f / CDIM) - mu * mu;
        smu[n] = mu;
        srs[n] = rsqrtf(fmaxf(var, 0.f) + 1e-5f);
    }
    __syncthreads();
    size_t ob = (size_t)win * NTOK * CDIM;
    for (int i = threadIdx.x; i < NTOK * CDIM; i += blockDim.x) {
        int n = i / CDIM, c = i - n * CDIM;
        float v = (tile[n * 193 + c] - smu[n]) * srs[n] * g[c] + b[c];
        g_S[ob + i] = v;
        __nv_bfloat16 hh, ll;
        splitf(v, hh, ll);
        g_Sh[ob + i] = hh;
        g_Sl[ob + i] = ll;
    }
}

// ---------------- LN2 normalize -> planes ----------------
__global__ void __launch_bounds__(256)
ln2_norm_kernel(const float* __restrict__ g, const float* __restrict__ b) {
    int r = blockIdx.x * 8 + (threadIdx.x >> 5);
    int lane = threadIdx.x & 31;
    const float* row = g_X2 + (size_t)r * CDIM;
    float2 v[3];
    float s = 0.f, ss = 0.f;
    #pragma unroll
    for (int i = 0; i < 3; i++) {
        v[i] = *reinterpret_cast<const float2*>(row + i * 64 + lane * 2);
        s += v[i].x + v[i].y;
        ss += v[i].x * v[i].x + v[i].y * v[i].y;
    }
    #pragma unroll
    for (int o = 16; o > 0; o >>= 1) {
        s  += __shfl_xor_sync(0xffffffffu, s,  o);
        ss += __shfl_xor_sync(0xffffffffu, ss, o);
    }
    float mu = s * (1.0f / CDIM);
    float var = ss * (1.0f / CDIM) - mu * mu;
    float rs = rsqrtf(fmaxf(var, 0.f) + 1e-5f);
    #pragma unroll
    for (int i = 0; i < 3; i++) {
        int c = i * 64 + lane * 2;
        float2 gg = *reinterpret_cast<const float2*>(g + c);
        float2 bb = *reinterpret_cast<const float2*>(b + c);
        float vx = (v[i].x - mu) * rs * gg.x + bb.x;
        float vy = (v[i].y - mu) * rs * gg.y + bb.y;
        __nv_bfloat16 hx, lx, hy, ly;
        splitf(vx, hx, lx);
        splitf(vy, hy, ly);
        __nv_bfloat162 hp = __halves2bfloat162(hx, hy);
        __nv_bfloat162 lp = __halves2bfloat162(lx, ly);
        *reinterpret_cast<__nv_bfloat162*>(g_Nh + (size_t)r * CDIM + c) = hp;
        *reinterpret_cast<__nv_bfloat162*>(g_Nl + (size_t)r * CDIM + c) = lp;
    }
}

// ---------------- attention ----------------
__global__ void __launch_bounds__(256)
attn_kernel(const float* __restrict__ rpb, const float* __restrict__ temp) {
    extern __shared__ float smf[];
    float* s_q = smf;
    float* s_k = s_q + 64 * 33;
    float* s_v = s_k + 64 * 33;
    float* s_a = s_v + 64 * 36;
    float* s_t = s_a + 64 * 65;

    int blk = blockIdx.x;
    int win = blk / HEADS;
    int h = blk - win * HEADS;
    int tid = threadIdx.x;
    int wid = tid >> 5, lane = tid & 31;

    for (int i = tid; i < 225 * HEADS; i += 256) s_t[i] = rpb[i];
    float tmp = temp[h];
    size_t base = (size_t)win * NTOK;

    for (int n = wid; n < NTOK; n += 8) {
        const float* qp = g_QKV + (base + n) * CH3 + h * HD;
        float qv = qp[lane];
        float kv = qp[192 + lane];
        float vv = qp[384 + lane];
        float qs = qv * qv, ks = kv * kv;
        #pragma unroll
        for (int o = 16; o > 0; o >>= 1) {
            qs += __shfl_xor_sync(0xffffffffu, qs, o);
            ks += __shfl_xor_sync(0xffffffffu, ks, o);
        }
        float qi = 1.0f / fmaxf(sqrtf(qs), 1e-12f);
        float ki = 1.0f / fmaxf(sqrtf(ks), 1e-12f);
        s_q[n * 33 + lane] = qv * qi;
        s_k[n * 33 + lane] = kv * ki;
        s_v[n * 36 + lane] = vv;
    }
    __syncthreads();

    {
        int n0 = (tid >> 4) << 2;
        int m0 = (tid & 15) << 2;
        float acc[4][4];
        #pragma unroll
        for (int i = 0; i < 4; i++)
            #pragma unroll
            for (int j = 0; j < 4; j++) acc[i][j] = 0.f;
        #pragma unroll 8
        for (int d = 0; d < HD; d++) {
            float a[4], b[4];
            #pragma unroll
            for (int i = 0; i < 4; i++) a[i] = s_q[(n0 + i) * 33 + d];
            #pragma unroll
            for (int j = 0; j < 4; j++) b[j] = s_k[(m0 + j) * 33 + d];
            #pragma unroll
            for (int i = 0; i < 4; i++)
                #pragma unroll
                for (int j = 0; j < 4; j++)
                    acc[i][j] = fmaf(a[i], b[j], acc[i][j]);
        }
        #pragma unroll
        for (int i = 0; i < 4; i++)
            #pragma unroll
            for (int j = 0; j < 4; j++)
                s_a[(n0 + i) * 65 + m0 + j] = acc[i][j] * tmp;
    }
    __syncthreads();

    for (int n = wid; n < NTOK; n += 8) {
        int iy = n >> 3, ix = n & 7;
        float r0 = s_a[n * 65 + lane];
        float r1 = s_a[n * 65 + 32 + lane];
        float v0 = r0, v1 = r1;
        #pragma unroll 1
        for (int it = 0; it < 15; it++) {
            float m = fmaxf(v0, v1);
            #pragma unroll
            for (int o = 16; o > 0; o >>= 1) m = fmaxf(m, __shfl_xor_sync(0xffffffffu, m, o));
            unsigned b0 = __ballot_sync(0xffffffffu, v0 == m);
            if (b0) {
                if (lane == (__ffs(b0) - 1)) v0 = -1e30f;
            } else {
                unsigned b1 = __ballot_sync(0xffffffffu, v1 == m);
                if (lane == (__ffs(b1) - 1)) v1 = -1e30f;
            }
        }
        float kth = fmaxf(v0, v1);
        #pragma unroll
        for (int o = 16; o > 0; o >>= 1) kth = fmaxf(kth, __shfl_xor_sync(0xffffffffu, kth, o));

        int m0 = lane, m1 = lane + 32;
        int jy = m0 >> 3, jx = m0 & 7;
        float e0 = ((r0 >= kth) ? r0 : -100.0f)
                 + s_t[((iy - jy + 7) * 15 + (ix - jx + 7)) * HEADS + h];
        jy = m1 >> 3; jx = m1 & 7;
        float e1 = ((r1 >= kth) ? r1 : -100.0f)
                 + s_t[((iy - jy + 7) * 15 + (ix - jx + 7)) * HEADS + h];

        float mx = fmaxf(e0, e1);
        #pragma unroll
        for (int o = 16; o > 0; o >>= 1) mx = fmaxf(mx, __shfl_xor_sync(0xffffffffu, mx, o));
        float p0 = expf(e0 - mx), p1 = expf(e1 - mx);
        float s = p0 + p1;
        #pragma unroll
        for (int o = 16; o > 0; o >>= 1) s += __shfl_xor_sync(0xffffffffu, s, o);
        float inv = 1.0f / s;
        s_a[n * 65 + lane]      = p0 * inv;
        s_a[n * 65 + 32 + lane] = p1 * inv;
    }
    __syncthreads();

    {
        int d0 = (tid & 7) << 2;
        int n0 = (tid >> 3) << 1;
        float a0[4] = {0.f, 0.f, 0.f, 0.f};
        float a1[4] = {0.f, 0.f, 0.f, 0.f};
        #pragma unroll 8
        for (int m = 0; m < NTOK; m++) {
            float p0 = s_a[n0 * 65 + m];
            float p1 = s_a[(n0 + 1) * 65 + m];
            float4 vv = *reinterpret_cast<const float4*>(&s_v[m * 36 + d0]);
            a0[0] = fmaf(p0, vv.x, a0[0]); a0[1] = fmaf(p0, vv.y, a0[1]);
            a0[2] = fmaf(p0, vv.z, a0[2]); a0[3] = fmaf(p0, vv.w, a0[3]);
            a1[0] = fmaf(p1, vv.x, a1[0]); a1[1] = fmaf(p1, vv.y, a1[1]);
            a1[2] = fmaf(p1, vv.z, a1[2]); a1[3] = fmaf(p1, vv.w, a1[3]);
        }
        size_t off0 = (base + n0) * CDIM + h * HD + d0;
        size_t off1 = off0 + CDIM;
        #pragma unroll
        for (int j = 0; j < 4; j++) {
            __nv_bfloat16 hh, ll;
            splitf(a0[j], hh, ll);
            g_Oh[off0 + j] = hh; g_Ol[off0 + j] = ll;
            splitf(a1[j], hh, ll);
            g_Oh[off1 + j] = hh; g_Ol[off1 + j] = ll;
        }
    }
}

// ---------------- final transpose: g_S (token-major Y) -> NCHW out ----------------
__global__ void __launch_bounds__(256)
out_tr_kernel(float* __restrict__ out) {
    extern __shared__ float smf[];
    float* tile = smf;  // 64 x 193
    int win = blockIdx.x;
    int bi = win >> 6, wy = (win >> 3) & 7, wx = win & 7;
    const float* src = g_S + (size_t)win * NTOK * CDIM;
    for (int i = threadIdx.x; i < NTOK * CDIM; i += 256) {
        int n = i / CDIM, c = i - n * CDIM;
        tile[n * 193 + c] = src[i];
    }
    __syncthreads();
    float* ob = out + (size_t)bi * CDIM * HW;
    for (int i = threadIdx.x; i < NTOK * CDIM; i += 256) {
        int c = i >> 6, n = i & 63;
        int iy = n >> 3, ix = n & 7;
        int hw = ((wy << 3) + iy) * IMGW + (wx << 3) + ix;
        ob[(size_t)c * HW + hw] = tile[n * 193 + c];
    }
}

// ---------------- launch ----------------
extern "C" void kernel_launch(void* const* d_in, const int* in_sizes, int n_in,
                              void* d_out, int out_size) {
    const float* x      = (const float*)d_in[0];
    const float* n1g    = (const float*)d_in[1];
    const float* n1b    = (const float*)d_in[2];
    const float* qkv_w  = (const float*)d_in[3];
    const float* qkv_b  = (const float*)d_in[4];
    const float* proj_w = (const float*)d_in[5];
    const float* proj_b = (const float*)d_in[6];
    const float* rpb    = (const float*)d_in[7];
    const float* temp   = (const float*)d_in[8];
    const float* n2g    = (const float*)d_in[9];
    const float* n2b    = (const float*)d_in[10];
    const float* fc1_w  = (const float*)d_in[11];
    const float* fc1_b  = (const float*)d_in[12];
    const float* fc2_w  = (const float*)d_in[13];
    const float* fc2_b  = (const float*)d_in[14];
    float* out = (float*)d_out;

    const int LN1_SMEM  = (64 * 193 + 128) * 4;
    const int ATTN_SMEM = (64 * 33 * 2 + 64 * 36 + 64 * 65 + 225 * 6) * 4;
    const int TR_SMEM   = 64 * 193 * 4;
    cudaFuncSetAttribute(ln1_kernel,    cudaFuncAttributeMaxDynamicSharedMemorySize, LN1_SMEM);
    cudaFuncSetAttribute(attn_kernel,   cudaFuncAttributeMaxDynamicSharedMemorySize, ATTN_SMEM);
    cudaFuncSetAttribute(out_tr_kernel, cudaFuncAttributeMaxDynamicSharedMemorySize, TR_SMEM);
    cudaFuncSetAttribute(gemm_mma<0, 192>, cudaFuncAttributeMaxDynamicSharedMemorySize, GSMEM);
    cudaFuncSetAttribute(gemm_mma<1, 192>, cudaFuncAttributeMaxDynamicSharedMemorySize, GSMEM);
    cudaFuncSetAttribute(gemm_mma<2, 192>, cudaFuncAttributeMaxDynamicSharedMemorySize, GSMEM);
    cudaFuncSetAttribute(gemm_mma<3, 768>, cudaFuncAttributeMaxDynamicSharedMemorySize, GSMEM);

    wconv_kernel<<<(WTOT / 4 + 255) / 256, 256>>>(qkv_w, proj_w, fc1_w, fc2_w);
    ln1_kernel<<<NWIN, 256, LN1_SMEM>>>(x, n1g, n1b);
    gemm_mma<0, 192><<<dim3(ROWS / 128, CH3 / 64), 256, GSMEM>>>(qkv_b);
    attn_kernel<<<NWIN * HEADS, 256, ATTN_SMEM>>>(rpb, temp);
    gemm_mma<1, 192><<<dim3(ROWS / 128, CDIM / 64), 256, GSMEM>>>(proj_b);
    ln2_norm_kernel<<<ROWS / 8, 256>>>(n2g, n2b);
    gemm_mma<2, 192><<<dim3(ROWS / 128, FF / 64), 256, GSMEM>>>(fc1_b);
    gemm_mma<3, 768><<<dim3(ROWS / 128, CDIM / 64), 256, GSMEM>>>(fc2_b);
    out_tr_kernel<<<NWIN, 256, TR_SMEM>>>(out);
}

// round 10
// speedup vs baseline: 1.8781x; 1.1905x over previous
#include <cuda_runtime.h>
#include <cuda_bf16.h>
#include <math.h>
#include <stdint.h>

// ---------------- problem constants ----------------
#define BATCH   8
#define CDIM    192
#define HEADS   6
#define HD      32
#define NTOK    64
#define NWIN    512
#define ROWS    32768
#define CH3     576
#define FF      768
#define HW      4096
#define IMGW    64

// weight plane offsets (elements)
#define OFF_QKV  0
#define OFF_PROJ 110592
#define OFF_FC1  147456
#define OFF_FC2  294912
#define WTOT     442368

// ---------------- scratch ----------------
__device__ float g_S  [ROWS * (size_t)CDIM];   // LN1 fp32 (shortcut); reused as final token-major Y
__device__ float g_QKV[ROWS * (size_t)CH3];
__device__ float g_X2 [ROWS * (size_t)CDIM];

__device__ __nv_bfloat16 g_Sh[ROWS * (size_t)CDIM], g_Sl[ROWS * (size_t)CDIM];
__device__ __nv_bfloat16 g_Oh[ROWS * (size_t)CDIM], g_Ol[ROWS * (size_t)CDIM];
__device__ __nv_bfloat16 g_Nh[ROWS * (size_t)CDIM], g_Nl[ROWS * (size_t)CDIM];
__device__ __nv_bfloat16 g_Hh[ROWS * (size_t)FF],   g_Hl[ROWS * (size_t)FF];
__device__ __nv_bfloat16 g_Wh[WTOT], g_Wl[WTOT];

// ---------------- helpers ----------------
__device__ __forceinline__ uint32_t smem_to_u32(const void* p) {
    uint32_t a;
    asm("{ .reg .u64 t; cvta.to.shared.u64 t, %1; cvt.u32.u64 %0, t; }" : "=r"(a) : "l"(p));
    return a;
}
__device__ __forceinline__ void ldm4(uint32_t* r, uint32_t addr) {
    asm volatile("ldmatrix.sync.aligned.m8n8.x4.shared.b16 {%0,%1,%2,%3}, [%4];"
                 : "=r"(r[0]), "=r"(r[1]), "=r"(r[2]), "=r"(r[3]) : "r"(addr));
}
__device__ __forceinline__ void mma_bf16(float* c, const uint32_t* a, uint32_t b0, uint32_t b1) {
    asm volatile("mma.sync.aligned.m16n8k16.row.col.f32.bf16.bf16.f32 "
                 "{%0,%1,%2,%3}, {%4,%5,%6,%7}, {%8,%9}, {%0,%1,%2,%3};"
                 : "+f"(c[0]), "+f"(c[1]), "+f"(c[2]), "+f"(c[3])
                 : "r"(a[0]), "r"(a[1]), "r"(a[2]), "r"(a[3]), "r"(b0), "r"(b1));
}
__device__ __forceinline__ void splitf(float v, __nv_bfloat16& h, __nv_bfloat16& l) {
    h = __float2bfloat16(v);
    l = __float2bfloat16(v - __bfloat162float(h));
}
__device__ __forceinline__ void split_pair(float x, float y, unsigned& h, unsigned& l) {
    __nv_bfloat16 hx, lx, hy, ly;
    splitf(x, hx, lx);
    splitf(y, hy, ly);
    __nv_bfloat162 hh = __halves2bfloat162(hx, hy);
    __nv_bfloat162 ll = __halves2bfloat162(lx, ly);
    h = *reinterpret_cast<unsigned*>(&hh);
    l = *reinterpret_cast<unsigned*>(&ll);
}
// monotonic float->u32 key (order-preserving)
__device__ __forceinline__ unsigned fkey(float v) {
    unsigned u = __float_as_uint(v);
    return (u & 0x80000000u) ? ~u : (u | 0x80000000u);
}
__device__ __forceinline__ float unfkey(unsigned k) {
    return __uint_as_float((k & 0x80000000u) ? (k & 0x7fffffffu) : ~k);
}
#define CP16(sdst, gsrc) \
    asm volatile("cp.async.ca.shared.global [%0], [%1], 16;" :: "r"(sdst), "l"(gsrc) : "memory")
#define CP_COMMIT() asm volatile("cp.async.commit_group;" ::: "memory")

// GEMM smem per stage (bytes): Ah 10240 | Al 10240 | Bh 5120 | Bl 5120
#define AH_OFF 0
#define AL_OFF 10240
#define BH_OFF 20480
#define BL_OFF 25600
#define STG    30720
#define GSMEM  61440

// ---------------- bf16x3 HMMA GEMM with cp.async pipeline ----------------
template<int MODE, int K>
__global__ void __launch_bounds__(256)
gemm_mma(const float* __restrict__ bias) {
    extern __shared__ char sm[];
    uint32_t sb = smem_to_u32(sm);

    const __nv_bfloat16* Ah_g = (MODE == 0) ? g_Sh : (MODE == 1) ? g_Oh : (MODE == 2) ? g_Nh : g_Hh;
    const __nv_bfloat16* Al_g = (MODE == 0) ? g_Sl : (MODE == 1) ? g_Ol : (MODE == 2) ? g_Nl : g_Hl;
    constexpr int WOFF = (MODE == 0) ? OFF_QKV : (MODE == 1) ? OFF_PROJ : (MODE == 2) ? OFF_FC1 : OFF_FC2;
    const __nv_bfloat16* Bh_g = g_Wh + WOFF;
    const __nv_bfloat16* Bl_g = g_Wl + WOFF;

    int tid = threadIdx.x;
    int lane = tid & 31, w = tid >> 5;
    int wm = (w >> 1) * 32, wn = (w & 1) * 32;
    int rbase = blockIdx.x * 128, cbase = blockIdx.y * 64;

    uint32_t aRow = (lane & 7) + ((lane >> 3) & 1) * 8;
    uint32_t aK   = (lane >> 4) * 8;
    uint32_t bN   = ((lane >> 4) & 1) * 8 + (lane & 7);
    uint32_t bK   = ((lane >> 3) & 1) * 8;

    float acc[2][4][4];
    #pragma unroll
    for (int mi = 0; mi < 2; mi++)
        #pragma unroll
        for (int ni = 0; ni < 4; ni++)
            #pragma unroll
            for (int j = 0; j < 4; j++) acc[mi][ni][j] = 0.f;

    auto copy_stage = [&](int st, int kt) {
        uint32_t base = sb + st * STG;
        #pragma unroll
        for (int i = 0; i < 2; i++) {
            int gq = i * 256 + tid;
            int r = gq >> 2, s2 = gq & 3;
            size_t go = (size_t)(rbase + r) * K + kt + s2 * 8;
            uint32_t so = (uint32_t)(r * 40 + s2 * 8) * 2;
            CP16(base + AH_OFF + so, Ah_g + go);
            CP16(base + AL_OFF + so, Al_g + go);
        }
        {
            int r = tid >> 2, s2 = tid & 3;
            size_t go = (size_t)(cbase + r) * K + kt + s2 * 8;
            uint32_t so = (uint32_t)(r * 40 + s2 * 8) * 2;
            CP16(base + BH_OFF + so, Bh_g + go);
            CP16(base + BL_OFF + so, Bl_g + go);
        }
        CP_COMMIT();
    };

    constexpr int NC = K / 32;
    copy_stage(0, 0);

    for (int c = 0; c < NC; c++) {
        if (c + 1 < NC) {
            copy_stage((c + 1) & 1, (c + 1) * 32);
            asm volatile("cp.async.wait_group 1;" ::: "memory");
        } else {
            asm volatile("cp.async.wait_group 0;" ::: "memory");
        }
        __syncthreads();

        uint32_t stb = sb + (c & 1) * STG;
        #pragma unroll
        for (int kk = 0; kk < 32; kk += 16) {
            uint32_t ah[2][4], al[2][4], bh[2][4], bl[2][4];
            #pragma unroll
            for (int mi = 0; mi < 2; mi++) {
                uint32_t off = ((wm + mi * 16 + aRow) * 40 + kk + aK) * 2;
                ldm4(ah[mi], stb + AH_OFF + off);
                ldm4(al[mi], stb + AL_OFF + off);
            }
            #pragma unroll
            for (int p = 0; p < 2; p++) {
                uint32_t off = ((wn + p * 16 + bN) * 40 + kk + bK) * 2;
                ldm4(bh[p], stb + BH_OFF + off);
                ldm4(bl[p], stb + BL_OFF + off);
            }
            #pragma unroll
            for (int mi = 0; mi < 2; mi++)
                #pragma unroll
                for (int ni = 0; ni < 4; ni++) {
                    int p = ni >> 1, o = (ni & 1) * 2;
                    mma_bf16(acc[mi][ni], ah[mi], bh[p][o], bh[p][o + 1]);
                    mma_bf16(acc[mi][ni], ah[mi], bl[p][o], bl[p][o + 1]);
                    mma_bf16(acc[mi][ni], al[mi], bh[p][o], bh[p][o + 1]);
                }
        }
        __syncthreads();
    }

    float* st = reinterpret_cast<float*>(sm);   // 128 x 65
    #pragma unroll
    for (int mi = 0; mi < 2; mi++)
        #pragma unroll
        for (int ni = 0; ni < 4; ni++) {
            int row = wm + mi * 16 + (lane >> 2);
            int col = wn + ni * 8 + (lane & 3) * 2;
            st[row * 65 + col]           = acc[mi][ni][0];
            st[row * 65 + col + 1]       = acc[mi][ni][1];
            st[(row + 8) * 65 + col]     = acc[mi][ni][2];
            st[(row + 8) * 65 + col + 1] = acc[mi][ni][3];
        }
    __syncthreads();

    for (int i = tid; i < 128 * 64; i += 256) {
        int row = i >> 6, j = i & 63;
        int r = rbase + row, cc = cbase + j;
        float v = st[row * 65 + j] + bias[cc];
        if (MODE == 0) {
            g_QKV[(size_t)r * CH3 + cc] = v;
        } else if (MODE == 1) {
            g_X2[(size_t)r * CDIM + cc] = g_S[(size_t)r * CDIM + cc] + v;
        } else if (MODE == 2) {
            float a = 0.5f * v * (1.0f + erff(v * 0.70710678118654752f));
            __nv_bfloat16 hh, ll;
            splitf(a, hh, ll);
            g_Hh[(size_t)r * FF + cc] = hh;
            g_Hl[(size_t)r * FF + cc] = ll;
        } else {
            g_S[(size_t)r * CDIM + cc] = g_X2[(size_t)r * CDIM + cc] + v;
        }
    }
}

// ---------------- weight conversion ----------------
__global__ void __launch_bounds__(256)
wconv_kernel(const float* __restrict__ qkv_w, const float* __restrict__ proj_w,
             const float* __restrict__ fc1_w, const float* __restrict__ fc2_w) {
    int idx = blockIdx.x * 256 + threadIdx.x;
    if (idx >= WTOT / 4) return;
    int i4 = idx * 4;
    const float* src;
    int off;
    if (i4 < OFF_PROJ)      { src = qkv_w;  off = i4; }
    else if (i4 < OFF_FC1)  { src = proj_w; off = i4 - OFF_PROJ; }
    else if (i4 < OFF_FC2)  { src = fc1_w;  off = i4 - OFF_FC1; }
    else                    { src = fc2_w;  off = i4 - OFF_FC2; }
    float4 v = *reinterpret_cast<const float4*>(src + off);
    __nv_bfloat16 h[4], l[4];
    splitf(v.x, h[0], l[0]); splitf(v.y, h[1], l[1]);
    splitf(v.z, h[2], l[2]); splitf(v.w, h[3], l[3]);
    *reinterpret_cast<uint2*>(g_Wh + i4) = *reinterpret_cast<uint2*>(h);
    *reinterpret_cast<uint2*>(g_Wl + i4) = *reinterpret_cast<uint2*>(l);
}

// ---------------- LN1 + window partition ----------------
__global__ void __launch_bounds__(256)
ln1_kernel(const float* __restrict__ x, const float* __restrict__ g,
           const float* __restrict__ b) {
    extern __shared__ float smf[];
    float* tile = smf;
    float* smu  = smf + 64 * 193;
    float* srs  = smu + 64;

    int win = blockIdx.x;
    int bi = win >> 6, wy = (win >> 3) & 7, wx = win & 7;
    const float* xb = x + (size_t)bi * CDIM * HW;

    for (int i = threadIdx.x; i < NTOK * CDIM; i += blockDim.x) {
        int c = i >> 6, n = i & 63;
        int iy = n >> 3, ix = n & 7;
        int hw = ((wy << 3) + iy) * IMGW + (wx << 3) + ix;
        tile[n * 193 + c] = xb[(size_t)c * HW + hw];
    }
    __syncthreads();
    if (threadIdx.x < NTOK) {
        int n = threadIdx.x;
        float s = 0.f, ss = 0.f;
        #pragma unroll 4
        for (int c = 0; c < CDIM; c++) {
            float v = tile[n * 193 + c];
            s += v; ss += v * v;
        }
        float mu = s * (1.0f / CDIM);
        float var = ss * (1.0f / CDIM) - mu * mu;
        smu[n] = mu;
        srs[n] = rsqrtf(fmaxf(var, 0.f) + 1e-5f);
    }
    __syncthreads();
    size_t ob = (size_t)win * NTOK * CDIM;
    for (int i = threadIdx.x; i < NTOK * CDIM; i += blockDim.x) {
        int n = i / CDIM, c = i - n * CDIM;
        float v = (tile[n * 193 + c] - smu[n]) * srs[n] * g[c] + b[c];
        g_S[ob + i] = v;
        __nv_bfloat16 hh, ll;
        splitf(v, hh, ll);
        g_Sh[ob + i] = hh;
        g_Sl[ob + i] = ll;
    }
}

// ---------------- LN2 normalize -> planes ----------------
__global__ void __launch_bounds__(256)
ln2_norm_kernel(const float* __restrict__ g, const float* __restrict__ b) {
    int r = blockIdx.x * 8 + (threadIdx.x >> 5);
    int lane = threadIdx.x & 31;
    const float* row = g_X2 + (size_t)r * CDIM;
    float2 v[3];
    float s = 0.f, ss = 0.f;
    #pragma unroll
    for (int i = 0; i < 3; i++) {
        v[i] = *reinterpret_cast<const float2*>(row + i * 64 + lane * 2);
        s += v[i].x + v[i].y;
        ss += v[i].x * v[i].x + v[i].y * v[i].y;
    }
    #pragma unroll
    for (int o = 16; o > 0; o >>= 1) {
        s  += __shfl_xor_sync(0xffffffffu, s,  o);
        ss += __shfl_xor_sync(0xffffffffu, ss, o);
    }
    float mu = s * (1.0f / CDIM);
    float var = ss * (1.0f / CDIM) - mu * mu;
    float rs = rsqrtf(fmaxf(var, 0.f) + 1e-5f);
    #pragma unroll
    for (int i = 0; i < 3; i++) {
        int c = i * 64 + lane * 2;
        float2 gg = *reinterpret_cast<const float2*>(g + c);
        float2 bb = *reinterpret_cast<const float2*>(b + c);
        float vx = (v[i].x - mu) * rs * gg.x + bb.x;
        float vy = (v[i].y - mu) * rs * gg.y + bb.y;
        unsigned hp, lp;
        split_pair(vx, vy, hp, lp);
        *reinterpret_cast<unsigned*>(g_Nh + (size_t)r * CDIM + c) = hp;
        *reinterpret_cast<unsigned*>(g_Nl + (size_t)r * CDIM + c) = lp;
    }
}

// ---------------- attention v2: HMMA logits/AV + redux topk ----------------
// smem layout (bytes):
#define A_QH  0        // 64*40*2 = 5120   (later aliased by PH/PL)
#define A_QL  5120
#define A_KH  10240
#define A_KL  15360
#define A_PH  0        // 64*72*2 = 9216
#define A_PL  9216
#define A_VTH 20480    // 32*72*2 = 4608
#define A_VTL 25088
#define A_SA  29696    // 64*65*4 = 16640 fp32  (aliased by s_v staging 64*37*4)
#define A_SV  29696
#define A_ST  46336    // 225*4
#define ATTN_SMEM 47296

__global__ void __launch_bounds__(256)
attn_kernel(const float* __restrict__ rpb, const float* __restrict__ temp) {
    extern __shared__ char smc[];
    uint32_t sb = smem_to_u32(smc);
    __nv_bfloat16* qh = reinterpret_cast<__nv_bfloat16*>(smc + A_QH);
    __nv_bfloat16* ql = reinterpret_cast<__nv_bfloat16*>(smc + A_QL);
    __nv_bfloat16* kh = reinterpret_cast<__nv_bfloat16*>(smc + A_KH);
    __nv_bfloat16* kl = reinterpret_cast<__nv_bfloat16*>(smc + A_KL);
    __nv_bfloat16* ph = reinterpret_cast<__nv_bfloat16*>(smc + A_PH);
    __nv_bfloat16* pl = reinterpret_cast<__nv_bfloat16*>(smc + A_PL);
    float* s_a = reinterpret_cast<float*>(smc + A_SA);
    float* s_v = reinterpret_cast<float*>(smc + A_SV);
    float* s_t = reinterpret_cast<float*>(smc + A_ST);

    int blk = blockIdx.x;
    int win = blk / HEADS;
    int h = blk - win * HEADS;
    int tid = threadIdx.x, lane = tid & 31, w = tid >> 5;
    size_t base = (size_t)win * NTOK;
    float tmp = temp[h];

    for (int i = tid; i < 225; i += 256) s_t[i] = rpb[i * HEADS + h];

    // ldmatrix lane patterns
    uint32_t aRow = lane & 15;
    uint32_t aK   = (lane >> 4) * 8;
    uint32_t bN   = ((lane >> 4) & 1) * 8 + (lane & 7);
    uint32_t bK   = ((lane >> 3) & 1) * 8;

    // ---- phase 1: load + l2norm q,k -> planes; v -> fp32 staging ----
    for (int n = w; n < NTOK; n += 8) {
        const float* qp = g_QKV + (base + n) * CH3 + h * HD;
        float qv = qp[lane], kv = qp[192 + lane], vv = qp[384 + lane];
        float qs = qv * qv, ks = kv * kv;
        #pragma unroll
        for (int o = 16; o > 0; o >>= 1) {
            qs += __shfl_xor_sync(0xffffffffu, qs, o);
            ks += __shfl_xor_sync(0xffffffffu, ks, o);
        }
        float qn = qv * (tmp / fmaxf(sqrtf(qs), 1e-12f));
        float kn = kv / fmaxf(sqrtf(ks), 1e-12f);
        __nv_bfloat16 hh, ll;
        splitf(qn, hh, ll);
        qh[n * 40 + lane] = hh; ql[n * 40 + lane] = ll;
        splitf(kn, hh, ll);
        kh[n * 40 + lane] = hh; kl[n * 40 + lane] = ll;
        s_v[n * 37 + lane] = vv;
    }
    __syncthreads();

    // ---- phase 2: build transposed V planes (d-major, stride 72) ----
    {
        int d = tid >> 3, m0 = (tid & 7) * 8;
        #pragma unroll
        for (int i = 0; i < 4; i++) {
            float a = s_v[(m0 + 2 * i) * 37 + d];
            float b = s_v[(m0 + 2 * i + 1) * 37 + d];
            unsigned hp, lp;
            split_pair(a, b, hp, lp);
            reinterpret_cast<unsigned*>(smc + A_VTH)[d * 36 + m0 / 2 + i] = hp;
            reinterpret_cast<unsigned*>(smc + A_VTL)[d * 36 + m0 / 2 + i] = lp;
        }
    }
    __syncthreads();

    // ---- phase 3: logits MMA (64x64x32, bf16x3) -> s_a fp32 ----
    {
        int mw = w & 1, nw = w >> 1;          // 2 x 4 warp grid, tile 32x16
        float c[2][2][4];
        #pragma unroll
        for (int mi = 0; mi < 2; mi++)
            #pragma unroll
            for (int nj = 0; nj < 2; nj++)
                #pragma unroll
                for (int j = 0; j < 4; j++) c[mi][nj][j] = 0.f;
        #pragma unroll
        for (int kk = 0; kk < 32; kk += 16) {
            uint32_t ah[2][4], al[2][4], bh[4], bl[4];
            #pragma unroll
            for (int mi = 0; mi < 2; mi++) {
                uint32_t off = ((mw * 32 + mi * 16 + aRow) * 40 + kk + aK) * 2;
                ldm4(ah[mi], sb + A_QH + off);
                ldm4(al[mi], sb + A_QL + off);
            }
            uint32_t boff = ((nw * 16 + bN) * 40 + kk + bK) * 2;
            ldm4(bh, sb + A_KH + boff);
            ldm4(bl, sb + A_KL + boff);
            #pragma unroll
            for (int mi = 0; mi < 2; mi++)
                #pragma unroll
                for (int nj = 0; nj < 2; nj++) {
                    mma_bf16(c[mi][nj], ah[mi], bh[2 * nj], bh[2 * nj + 1]);
                    mma_bf16(c[mi][nj], ah[mi], bl[2 * nj], bl[2 * nj + 1]);
                    mma_bf16(c[mi][nj], al[mi], bh[2 * nj], bh[2 * nj + 1]);
                }
        }
        #pragma unroll
        for (int mi = 0; mi < 2; mi++)
            #pragma unroll
            for (int nj = 0; nj < 2; nj++) {
                int r = mw * 32 + mi * 16 + (lane >> 2);
                int cc = nw * 16 + nj * 8 + (lane & 3) * 2;
                s_a[r * 65 + cc]           = c[mi][nj][0];
                s_a[r * 65 + cc + 1]       = c[mi][nj][1];
                s_a[(r + 8) * 65 + cc]     = c[mi][nj][2];
                s_a[(r + 8) * 65 + cc + 1] = c[mi][nj][3];
            }
    }
    __syncthreads();

    // ---- phase 4: top-16 (redux removal) + rpb + softmax -> p planes ----
    {
        int jy0 = lane >> 3, jx0 = lane & 7;
        int jy1 = (lane + 32) >> 3, jx1 = lane & 7;
        for (int pr = w; pr < 32; pr += 8) {
            int na = pr * 2, nb = na + 1;
            float ra0 = s_a[na * 65 + lane], ra1 = s_a[na * 65 + 32 + lane];
            float rb0 = s_a[nb * 65 + lane], rb1 = s_a[nb * 65 + 32 + lane];
            unsigned oa0 = fkey(ra0), oa1 = fkey(ra1);
            unsigned ob0 = fkey(rb0), ob1 = fkey(rb1);
            unsigned ka0 = oa0, ka1 = oa1, kb0 = ob0, kb1 = ob1;
            #pragma unroll 1
            for (int it = 0; it < 15; it++) {
                unsigned ma = __reduce_max_sync(0xffffffffu, ka0 > ka1 ? ka0 : ka1);
                unsigned mb = __reduce_max_sync(0xffffffffu, kb0 > kb1 ? kb0 : kb1);
                bool a0 = (ka0 == ma), a1 = !a0 && (ka1 == ma);
                bool b0 = (kb0 == mb), b1 = !b0 && (kb1 == mb);
                unsigned ba = __ballot_sync(0xffffffffu, a0 || a1);
                unsigned bb = __ballot_sync(0xffffffffu, b0 || b1);
                if (lane == (unsigned)(__ffs(ba) - 1)) { if (a0) ka0 = 0u; else ka1 = 0u; }
                if (lane == (unsigned)(__ffs(bb) - 1)) { if (b0) kb0 = 0u; else kb1 = 0u; }
            }
            unsigned kta = __reduce_max_sync(0xffffffffu, ka0 > ka1 ? ka0 : ka1);
            unsigned ktb = __reduce_max_sync(0xffffffffu, kb0 > kb1 ? kb0 : kb1);

            int iya = na >> 3, ixa = na & 7;
            int iyb = nb >> 3, ixb = nb & 7;
            float ea0 = ((oa0 >= kta) ? ra0 : -100.0f) + s_t[(iya - jy0 + 7) * 15 + (ixa - jx0 + 7)];
            float ea1 = ((oa1 >= kta) ? ra1 : -100.0f) + s_t[(iya - jy1 + 7) * 15 + (ixa - jx1 + 7)];
            float eb0 = ((ob0 >= ktb) ? rb0 : -100.0f) + s_t[(iyb - jy0 + 7) * 15 + (ixb - jx0 + 7)];
            float eb1 = ((ob1 >= ktb) ? rb1 : -100.0f) + s_t[(iyb - jy1 + 7) * 15 + (ixb - jx1 + 7)];

            unsigned mka = __reduce_max_sync(0xffffffffu, fkey(fmaxf(ea0, ea1)));
            unsigned mkb = __reduce_max_sync(0xffffffffu, fkey(fmaxf(eb0, eb1)));
            float mxa = unfkey(mka), mxb = unfkey(mkb);
            float pa0 = expf(ea0 - mxa), pa1 = expf(ea1 - mxa);
            float pb0 = expf(eb0 - mxb), pb1 = expf(eb1 - mxb);
            float sa = pa0 + pa1, sbm = pb0 + pb1;
            #pragma unroll
            for (int o = 16; o > 0; o >>= 1) {
                sa  += __shfl_xor_sync(0xffffffffu, sa,  o);
                sbm += __shfl_xor_sync(0xffffffffu, sbm, o);
            }
            float ia = 1.0f / sa, ib = 1.0f / sbm;
            __nv_bfloat16 hh, ll;
            splitf(pa0 * ia, hh, ll); ph[na * 72 + lane] = hh;      pl[na * 72 + lane] = ll;
            splitf(pa1 * ia, hh, ll); ph[na * 72 + 32 + lane] = hh; pl[na * 72 + 32 + lane] = ll;
            splitf(pb0 * ib, hh, ll); ph[nb * 72 + lane] = hh;      pl[nb * 72 + lane] = ll;
            splitf(pb1 * ib, hh, ll); ph[nb * 72 + 32 + lane] = hh; pl[nb * 72 + 32 + lane] = ll;
        }
    }
    __syncthreads();

    // ---- phase 5: AV MMA (64x32x64, bf16x3) -> g_Oh/g_Ol ----
    {
        int mw = w >> 1, dw = w & 1;          // 4 x 2 warp grid, tile 16x16
        float c[2][4];
        #pragma unroll
        for (int nj = 0; nj < 2; nj++)
            #pragma unroll
            for (int j = 0; j < 4; j++) c[nj][j] = 0.f;
        #pragma unroll
        for (int kk = 0; kk < 64; kk += 16) {
            uint32_t ahh[4], all[4], bh[4], bl[4];
            uint32_t aoff = ((mw * 16 + aRow) * 72 + kk + aK) * 2;
            ldm4(ahh, sb + A_PH + aoff);
            ldm4(all, sb + A_PL + aoff);
            uint32_t boff = ((dw * 16 + bN) * 72 + kk + bK) * 2;
            ldm4(bh, sb + A_VTH + boff);
            ldm4(bl, sb + A_VTL + boff);
            #pragma unroll
            for (int nj = 0; nj < 2; nj++) {
                mma_bf16(c[nj], ahh, bh[2 * nj], bh[2 * nj + 1]);
                mma_bf16(c[nj], ahh, bl[2 * nj], bl[2 * nj + 1]);
                mma_bf16(c[nj], all, bh[2 * nj], bh[2 * nj + 1]);
            }
        }
        #pragma unroll
        for (int nj = 0; nj < 2; nj++) {
            int r0 = mw * 16 + (lane >> 2);
            int dloc = dw * 16 + nj * 8 + (lane & 3) * 2;
            size_t o0 = (base + r0) * CDIM + h * HD + dloc;
            size_t o1 = (base + r0 + 8) * CDIM + h * HD + dloc;
            unsigned hp, lp;
            split_pair(c[nj][0], c[nj][1], hp, lp);
            *reinterpret_cast<unsigned*>(g_Oh + o0) = hp;
            *reinterpret_cast<unsigned*>(g_Ol + o0) = lp;
            split_pair(c[nj][2], c[nj][3], hp, lp);
            *reinterpret_cast<unsigned*>(g_Oh + o1) = hp;
            *reinterpret_cast<unsigned*>(g_Ol + o1) = lp;
        }
    }
}

// ---------------- final transpose: g_S (token-major Y) -> NCHW out ----------------
__global__ void __launch_bounds__(256)
out_tr_kernel(float* __restrict__ out) {
    extern __shared__ float smf[];
    float* tile = smf;  // 64 x 193
    int win = blockIdx.x;
    int bi = win >> 6, wy = (win >> 3) & 7, wx = win & 7;
    const float* src = g_S + (size_t)win * NTOK * CDIM;
    for (int i = threadIdx.x; i < NTOK * CDIM; i += 256) {
        int n = i / CDIM, c = i - n * CDIM;
        tile[n * 193 + c] = src[i];
    }
    __syncthreads();
    float* ob = out + (size_t)bi * CDIM * HW;
    for (int i = threadIdx.x; i < NTOK * CDIM; i += 256) {
        int c = i >> 6, n = i & 63;
        int iy = n >> 3, ix = n & 7;
        int hw = ((wy << 3) + iy) * IMGW + (wx << 3) + ix;
        ob[(size_t)c * HW + hw] = tile[n * 193 + c];
    }
}

// ---------------- launch ----------------
extern "C" void kernel_launch(void* const* d_in, const int* in_sizes, int n_in,
                              void* d_out, int out_size) {
    const float* x      = (const float*)d_in[0];
    const float* n1g    = (const float*)d_in[1];
    const float* n1b    = (const float*)d_in[2];
    const float* qkv_w  = (const float*)d_in[3];
    const float* qkv_b  = (const float*)d_in[4];
    const float* proj_w = (const float*)d_in[5];
    const float* proj_b = (const float*)d_in[6];
    const float* rpb    = (const float*)d_in[7];
    const float* temp   = (const float*)d_in[8];
    const float* n2g    = (const float*)d_in[9];
    const float* n2b    = (const float*)d_in[10];
    const float* fc1_w  = (const float*)d_in[11];
    const float* fc1_b  = (const float*)d_in[12];
    const float* fc2_w  = (const float*)d_in[13];
    const float* fc2_b  = (const float*)d_in[14];
    float* out = (float*)d_out;

    const int LN1_SMEM  = (64 * 193 + 128) * 4;
    const int TR_SMEM   = 64 * 193 * 4;
    cudaFuncSetAttribute(ln1_kernel,    cudaFuncAttributeMaxDynamicSharedMemorySize, LN1_SMEM);
    cudaFuncSetAttribute(attn_kernel,   cudaFuncAttributeMaxDynamicSharedMemorySize, ATTN_SMEM);
    cudaFuncSetAttribute(out_tr_kernel, cudaFuncAttributeMaxDynamicSharedMemorySize, TR_SMEM);
    cudaFuncSetAttribute(gemm_mma<0, 192>, cudaFuncAttributeMaxDynamicSharedMemorySize, GSMEM);
    cudaFuncSetAttribute(gemm_mma<1, 192>, cudaFuncAttributeMaxDynamicSharedMemorySize, GSMEM);
    cudaFuncSetAttribute(gemm_mma<2, 192>, cudaFuncAttributeMaxDynamicSharedMemorySize, GSMEM);
    cudaFuncSetAttribute(gemm_mma<3, 768>, cudaFuncAttributeMaxDynamicSharedMemorySize, GSMEM);

    wconv_kernel<<<(WTOT / 4 + 255) / 256, 256>>>(qkv_w, proj_w, fc1_w, fc2_w);
    ln1_kernel<<<NWIN, 256, LN1_SMEM>>>(x, n1g, n1b);
    gemm_mma<0, 192><<<dim3(ROWS / 128, CH3 / 64), 256, GSMEM>>>(qkv_b);
    attn_kernel<<<NWIN * HEADS, 256, ATTN_SMEM>>>(rpb, temp);
    gemm_mma<1, 192><<<dim3(ROWS / 128, CDIM / 64), 256, GSMEM>>>(proj_b);
    ln2_norm_kernel<<<ROWS / 8, 256>>>(n2g, n2b);
    gemm_mma<2, 192><<<dim3(ROWS / 128, FF / 64), 256, GSMEM>>>(fc1_b);
    gemm_mma<3, 768><<<dim3(ROWS / 128, CDIM / 64), 256, GSMEM>>>(fc2_b);
    out_tr_kernel<<<NWIN, 256, TR_SMEM>>>(out);
}